// round 7
// baseline (speedup 1.0000x reference)
#include <cuda_runtime.h>
#include <cuda_bf16.h>

#define BB 16
#define CC 528
#define TT 32
#define HH 28
#define WW 28
#define HW 784          // 28*28
#define HW4 196         // HW/4 (7 float4 groups per row)
#define RR 256
#define PLANE_F (TT*HW) // 25088 floats per (b,c)
#define MAX_ITEMS (BB*CC*HW4)   // 1,655,808
#define MEAN_BLOCKS ((MAX_ITEMS + 255) / 256)  // 6468

// ---- device scratch (no allocations allowed) ----
__device__ float  g_wmap[RR * HW];    // per-ROI dense weight map over 28x28
__device__ int4   g_rect[RR];         // xmin, xmax, ymin, ymax (inclusive); xmin>xmax => empty
__device__ int    g_list[BB][RR];     // ROI indices per batch
__device__ int    g_cnt[BB];
__device__ float  g_rmean[RR * CC];   // pooled ROI features
__device__ float  g_v[128];           // folded w3 @ w2  (layers 2+3 are linear)
__device__ float  g_c0;               // folded bias
__device__ float  g_part[RR * 16];    // per-(roi, j-group) partial sums
__device__ int    g_load[BB][HW4];    // per-batch compacted float4-group indices
__device__ int    g_nload[BB];        // count per batch
__device__ int    g_off[BB + 1];      // prefix of n4[b]*CC (flat work items)
__device__ float4 g_feat4[BB * CC * HW4];  // temporal-mean features (26.5 MB, L2-resident)

// ============================================================
// Kernel 0: build per-ROI weight map + nonzero rect.
// ============================================================
__global__ void wmap_kernel(const float* __restrict__ bbox) {
    __shared__ float smap[HW];
    __shared__ int sxmin, sxmax, symin, symax;
    const int roi = blockIdx.x;
    const int tid = threadIdx.x;

    for (int p = tid; p < HW; p += 256) smap[p] = 0.f;
    if (tid == 0) { sxmin = 1000; symin = 1000; sxmax = -1; symax = -1; }
    __syncthreads();

    const float* bb = bbox + roi * 5;
    const float x1 = bb[1] * 0.0625f - 0.5f;
    const float y1 = bb[2] * 0.0625f - 0.5f;
    const float x2 = bb[3] * 0.0625f - 0.5f;
    const float y2 = bb[4] * 0.0625f - 0.5f;
    const float bw = (x2 - x1) * 0.125f;   // /OUT(8)
    const float bh = (y2 - y1) * 0.125f;

    const int iy = tid >> 4, ix = tid & 15;
    const float sy = y1 + ((float)iy * 0.5f + 0.25f) * bh;  // off=(i+0.5)/SR
    const float sx = x1 + ((float)ix * 0.5f + 0.25f) * bw;

    const bool valid = (sy > -1.0f) && (sy < (float)HH) && (sx > -1.0f) && (sx < (float)WW);
    if (valid) {
        float yc = fminf(fmaxf(sy, 0.f), (float)(HH - 1));
        float xc = fminf(fmaxf(sx, 0.f), (float)(WW - 1));
        int y0 = (int)floorf(yc);
        int x0 = (int)floorf(xc);
        int y1i = min(y0 + 1, HH - 1);
        int x1i = min(x0 + 1, WW - 1);
        float ly = yc - (float)y0, lx = xc - (float)x0;
        float hy = 1.f - ly, hx = 1.f - lx;
        const float s = 1.0f / 256.0f;   // uniform mean over 16x16 samples
        atomicAdd(&smap[y0 * WW + x0],  hy * hx * s);
        atomicAdd(&smap[y0 * WW + x1i], hy * lx * s);
        atomicAdd(&smap[y1i * WW + x0], ly * hx * s);
        atomicAdd(&smap[y1i * WW + x1i], ly * lx * s);
        atomicMin(&sxmin, x0); atomicMax(&sxmax, x1i);
        atomicMin(&symin, y0); atomicMax(&symax, y1i);
    }
    __syncthreads();

    for (int p = tid; p < HW; p += 256) g_wmap[roi * HW + p] = smap[p];
    if (tid == 0) g_rect[roi] = make_int4(sxmin, sxmax, symin, symax);
}

// ============================================================
// Kernel 1: per-batch ROI lists + folded v = w3@w2, c0 = w3@b2 + b3.
// ============================================================
__global__ void prep_kernel(const float* __restrict__ bbox,
                            const float* __restrict__ w2,
                            const float* __restrict__ b2,
                            const float* __restrict__ w3,
                            const float* __restrict__ b3) {
    if (blockIdx.x == 0) {
        int b = threadIdx.x;
        if (b < BB) {
            int cnt = 0;
            for (int r = 0; r < RR; ++r) {
                int rb = (int)bbox[r * 5];
                if (rb == b) g_list[b][cnt++] = r;
            }
            g_cnt[b] = cnt;
        }
    } else {
        int j = threadIdx.x;
        if (j < 128) {
            float acc = 0.f;
            #pragma unroll
            for (int i = 0; i < 32; ++i) acc += w3[i] * w2[i * 128 + j];
            g_v[j] = acc;
            if (j == 0) {
                float c = b3[0];
                #pragma unroll
                for (int i = 0; i < 32; ++i) c += w3[i] * b2[i];
                g_c0 = c;
            }
        }
    }
}

// ============================================================
// Kernel 1b: single block. Per-batch union of ROI rects at float4
// granularity, compacted load lists, and flat-work-item prefix.
// ============================================================
__global__ void cover_kernel() {
    __shared__ unsigned char mask[HW4];
    const int tid = threadIdx.x;

    for (int b = 0; b < BB; ++b) {
        for (int i = tid; i < HW4; i += 256) mask[i] = 0;
        __syncthreads();

        const int n = g_cnt[b];
        for (int r = 0; r < n; ++r) {
            const int4 rc = g_rect[g_list[b][r]];
            if (rc.x > rc.y) continue;
            const int g0 = rc.x >> 2, g1 = rc.y >> 2;
            const int cols = g1 - g0 + 1;
            const int tot = (rc.w - rc.z + 1) * cols;
            for (int i = tid; i < tot; i += 256) {
                int ry = i / cols, cx = i - ry * cols;
                mask[(rc.z + ry) * 7 + g0 + cx] = 1;   // idempotent
            }
        }
        __syncthreads();

        if (tid == 0) {
            int cnt = 0;
            for (int i = 0; i < HW4; ++i)
                if (mask[i]) g_load[b][cnt++] = i;
            g_nload[b] = cnt;
        }
        __syncthreads();
    }
    if (tid == 0) {
        int acc = 0;
        for (int b = 0; b < BB; ++b) {
            g_off[b] = acc;
            acc += g_nload[b] * CC;
        }
        g_off[BB] = acc;
    }
}

// ============================================================
// Kernel 2 (HBM-bound, pure stream): temporal mean over covered groups.
// Flat work list: item -> (b, c, covered group). Every thread loads 32
// float4s (4 independent accumulator chains) and writes one feat group.
// No smem, no syncs, no idle threads.
// ============================================================
__global__ void __launch_bounds__(256) mean_kernel(const float* __restrict__ x) {
    __shared__ int soff[BB + 1];
    __shared__ int sn4[BB];
    if (threadIdx.x <= BB) soff[threadIdx.x] = g_off[threadIdx.x];
    if (threadIdx.x < BB)  sn4[threadIdx.x]  = g_nload[threadIdx.x];
    __syncthreads();

    const int item = blockIdx.x * 256 + threadIdx.x;
    if (item >= soff[BB]) return;

    int b = 0;
    while (item >= soff[b + 1]) ++b;
    const int rel = item - soff[b];
    const int n4 = sn4[b];
    const int c = rel / n4;
    const int j = rel - c * n4;
    const int p4 = g_load[b][j];
    const int plane = b * CC + c;

    const float4* __restrict__ xp =
        (const float4*)x + (size_t)plane * (TT * HW4) + p4;

    float4 a0 = make_float4(0.f, 0.f, 0.f, 0.f);
    float4 a1 = a0, a2 = a0, a3 = a0;
    #pragma unroll
    for (int t = 0; t < 8; ++t) {
        float4 v0 = __ldcs(xp + (t)      * HW4);
        float4 v1 = __ldcs(xp + (t + 8)  * HW4);
        float4 v2 = __ldcs(xp + (t + 16) * HW4);
        float4 v3 = __ldcs(xp + (t + 24) * HW4);
        a0.x += v0.x; a0.y += v0.y; a0.z += v0.z; a0.w += v0.w;
        a1.x += v1.x; a1.y += v1.y; a1.z += v1.z; a1.w += v1.w;
        a2.x += v2.x; a2.y += v2.y; a2.z += v2.z; a2.w += v2.w;
        a3.x += v3.x; a3.y += v3.y; a3.z += v3.z; a3.w += v3.w;
    }
    const float inv = 1.0f / (float)TT;
    g_feat4[(size_t)plane * HW4 + p4] = make_float4(
        (a0.x + a1.x + a2.x + a3.x) * inv,
        (a0.y + a1.y + a2.y + a3.y) * inv,
        (a0.z + a1.z + a2.z + a3.z) * inv,
        (a0.w + a1.w + a2.w + a3.w) * inv);
}

// ============================================================
// Kernel 2b: ROI pooling from L2-resident feat.
// One block per (b,c): stage covered plane in smem, warp-per-ROI dots.
// ============================================================
__global__ void __launch_bounds__(256) roi_kernel() {
    __shared__ float plane[HW];
    const int blk = blockIdx.x;            // b*CC + c
    const int b = blk / CC;
    const int c = blk - b * CC;
    const int tid = threadIdx.x;

    const int n4 = g_nload[b];
    if (tid < n4) {
        const int p4 = g_load[b][tid];
        ((float4*)plane)[p4] = g_feat4[(size_t)blk * HW4 + p4];
    }
    __syncthreads();
    // uncovered plane entries are uninitialized but never read (rects ⊆ union)

    const int nroi = g_cnt[b];
    const int warp = tid >> 5, lane = tid & 31;
    for (int r = warp; r < nroi; r += 8) {
        const int roi = g_list[b][r];
        const int4 rc = g_rect[roi];       // xmin xmax ymin ymax
        float acc = 0.f;
        if (rc.x <= rc.y) {
            const int xx = rc.x + lane;    // width <= 28 < 32
            const bool on = (xx <= rc.y);
            const float* __restrict__ wm = g_wmap + roi * HW;
            for (int yy = rc.z; yy <= rc.w; ++yy) {
                int p = yy * WW + xx;
                if (on) acc += wm[p] * plane[p];
            }
        }
        #pragma unroll
        for (int o = 16; o; o >>= 1) acc += __shfl_xor_sync(0xffffffffu, acc, o);
        if (lane == 0) g_rmean[roi * CC + c] = acc;
    }
}

// ============================================================
// Kernel 3: layer-1 GEMV partials, 16-way j-split (1024 blocks).
// Warp w of block (q, jg) handles neuron j = jg*8 + w for 4 ROIs.
// ============================================================
__global__ void __launch_bounds__(256) mlp_kernel(
    const float* __restrict__ w1, const float* __restrict__ b1) {
    __shared__ float r[4 * CC];
    __shared__ float part[8][4];
    const int tid = threadIdx.x, warp = tid >> 5, lane = tid & 31;
    const int roi0 = blockIdx.x * 4;
    const int jg = blockIdx.y;

    for (int i = tid; i < 4 * CC; i += 256)
        r[i] = g_rmean[roi0 * CC + i];
    __syncthreads();

    const int j = jg * 8 + warp;
    const float* __restrict__ wr = w1 + j * CC;

    float a0 = 0.f, a1 = 0.f, a2 = 0.f, a3 = 0.f;
    #pragma unroll 4
    for (int k = lane; k < CC; k += 32) {
        float w = wr[k];
        a0 += w * r[k];
        a1 += w * r[CC + k];
        a2 += w * r[2 * CC + k];
        a3 += w * r[3 * CC + k];
    }
    #pragma unroll
    for (int o = 16; o; o >>= 1) {
        a0 += __shfl_xor_sync(0xffffffffu, a0, o);
        a1 += __shfl_xor_sync(0xffffffffu, a1, o);
        a2 += __shfl_xor_sync(0xffffffffu, a2, o);
        a3 += __shfl_xor_sync(0xffffffffu, a3, o);
    }
    if (lane == 0) {
        float bj = b1[j], vj = g_v[j];
        part[warp][0] = vj * fmaxf(a0 + bj, 0.f);
        part[warp][1] = vj * fmaxf(a1 + bj, 0.f);
        part[warp][2] = vj * fmaxf(a2 + bj, 0.f);
        part[warp][3] = vj * fmaxf(a3 + bj, 0.f);
    }
    __syncthreads();
    if (tid < 4) {
        float s = 0.f;
        #pragma unroll
        for (int w = 0; w < 8; ++w) s += part[w][tid];
        g_part[(roi0 + tid) * 16 + jg] = s;
    }
}

// ============================================================
// Kernel 4: finalize. out[roi] = c0 + sum_jg part[roi][jg].
// ============================================================
__global__ void fin_kernel(float* __restrict__ out) {
    int roi = threadIdx.x;
    float s = g_c0;
    #pragma unroll
    for (int jg = 0; jg < 16; ++jg) s += g_part[roi * 16 + jg];
    out[roi] = s;
}

// ============================================================
// launch
// ============================================================
extern "C" void kernel_launch(void* const* d_in, const int* in_sizes, int n_in,
                              void* d_out, int out_size) {
    const float* x    = (const float*)d_in[0];
    const float* bbox = (const float*)d_in[1];
    const float* w1   = (const float*)d_in[2];
    const float* b1   = (const float*)d_in[3];
    const float* w2   = (const float*)d_in[4];
    const float* b2   = (const float*)d_in[5];
    const float* w3   = (const float*)d_in[6];
    const float* b3   = (const float*)d_in[7];
    float* out = (float*)d_out;

    wmap_kernel<<<RR, 256>>>(bbox);
    prep_kernel<<<2, 128>>>(bbox, w2, b2, w3, b3);
    cover_kernel<<<1, 256>>>();
    mean_kernel<<<MEAN_BLOCKS, 256>>>(x);
    roi_kernel<<<BB * CC, 256>>>();
    mlp_kernel<<<dim3(RR / 4, 16), 256>>>(w1, b1);
    fin_kernel<<<1, RR>>>(out);
}

// round 8
// speedup vs baseline: 1.6252x; 1.6252x over previous
#include <cuda_runtime.h>
#include <cuda_bf16.h>

#define BB 16
#define CC 528
#define TT 32
#define HH 28
#define WW 28
#define HW 784          // 28*28
#define HW4 196         // HW/4 (7 float4 groups per row)
#define RR 256
#define MAX_ITEMS (BB*CC*HW4)   // 1,655,808
#define MEAN_BLOCKS ((MAX_ITEMS + 255) / 256)  // 6468
#define CPB 24          // channels per roi-block (22 * 24 = 528)

// ---- device scratch (no allocations allowed) ----
__device__ float  g_wmap[RR * HW];    // per-ROI dense weight map over 28x28
__device__ int4   g_rect[RR];         // xmin, xmax, ymin, ymax (inclusive); xmin>xmax => empty
__device__ int    g_list[BB][RR];     // ROI indices per batch
__device__ int    g_cnt[BB];
__device__ int    g_broi[RR];         // batch index per roi
__device__ float  g_rmean[RR * CC];   // pooled ROI features
__device__ float  g_v[128];           // folded w3 @ w2  (layers 2+3 are linear)
__device__ float  g_c0;               // folded bias
__device__ float  g_part[RR * 16];    // per-(roi, j-group) partial sums
__device__ int    g_load[BB][HW4];    // per-batch compacted float4-group indices
__device__ int    g_nload[BB];        // count per batch
__device__ float4 g_feat4[BB * CC * HW4];  // temporal-mean features (26.5 MB, L2-resident)

// ============================================================
// Kernel 0: build per-ROI weight map + nonzero rect.
// ============================================================
__global__ void wmap_kernel(const float* __restrict__ bbox) {
    __shared__ float smap[HW];
    __shared__ int sxmin, sxmax, symin, symax;
    const int roi = blockIdx.x;
    const int tid = threadIdx.x;

    for (int p = tid; p < HW; p += 256) smap[p] = 0.f;
    if (tid == 0) { sxmin = 1000; symin = 1000; sxmax = -1; symax = -1; }
    __syncthreads();

    const float* bb = bbox + roi * 5;
    const float x1 = bb[1] * 0.0625f - 0.5f;
    const float y1 = bb[2] * 0.0625f - 0.5f;
    const float x2 = bb[3] * 0.0625f - 0.5f;
    const float y2 = bb[4] * 0.0625f - 0.5f;
    const float bw = (x2 - x1) * 0.125f;   // /OUT(8)
    const float bh = (y2 - y1) * 0.125f;

    const int iy = tid >> 4, ix = tid & 15;
    const float sy = y1 + ((float)iy * 0.5f + 0.25f) * bh;  // off=(i+0.5)/SR
    const float sx = x1 + ((float)ix * 0.5f + 0.25f) * bw;

    const bool valid = (sy > -1.0f) && (sy < (float)HH) && (sx > -1.0f) && (sx < (float)WW);
    if (valid) {
        float yc = fminf(fmaxf(sy, 0.f), (float)(HH - 1));
        float xc = fminf(fmaxf(sx, 0.f), (float)(WW - 1));
        int y0 = (int)floorf(yc);
        int x0 = (int)floorf(xc);
        int y1i = min(y0 + 1, HH - 1);
        int x1i = min(x0 + 1, WW - 1);
        float ly = yc - (float)y0, lx = xc - (float)x0;
        float hy = 1.f - ly, hx = 1.f - lx;
        const float s = 1.0f / 256.0f;   // uniform mean over 16x16 samples
        atomicAdd(&smap[y0 * WW + x0],  hy * hx * s);
        atomicAdd(&smap[y0 * WW + x1i], hy * lx * s);
        atomicAdd(&smap[y1i * WW + x0], ly * hx * s);
        atomicAdd(&smap[y1i * WW + x1i], ly * lx * s);
        atomicMin(&sxmin, x0); atomicMax(&sxmax, x1i);
        atomicMin(&symin, y0); atomicMax(&symax, y1i);
    }
    __syncthreads();

    for (int p = tid; p < HW; p += 256) g_wmap[roi * HW + p] = smap[p];
    if (tid == 0) {
        g_rect[roi] = make_int4(sxmin, sxmax, symin, symax);
        g_broi[roi] = (int)bb[0];
    }
}

// ============================================================
// Kernel 1: per-batch ROI lists + folded v = w3@w2, c0 = w3@b2 + b3.
// ============================================================
__global__ void prep_kernel(const float* __restrict__ bbox,
                            const float* __restrict__ w2,
                            const float* __restrict__ b2,
                            const float* __restrict__ w3,
                            const float* __restrict__ b3) {
    if (blockIdx.x == 0) {
        int b = threadIdx.x;
        if (b < BB) {
            int cnt = 0;
            for (int r = 0; r < RR; ++r) {
                int rb = (int)bbox[r * 5];
                if (rb == b) g_list[b][cnt++] = r;
            }
            g_cnt[b] = cnt;
        }
    } else {
        int j = threadIdx.x;
        if (j < 128) {
            float acc = 0.f;
            #pragma unroll
            for (int i = 0; i < 32; ++i) acc += w3[i] * w2[i * 128 + j];
            g_v[j] = acc;
            if (j == 0) {
                float c = b3[0];
                #pragma unroll
                for (int i = 0; i < 32; ++i) c += w3[i] * b2[i];
                g_c0 = c;
            }
        }
    }
}

// ============================================================
// Kernel 1b: per-batch union of ROI rects at float4-group granularity.
// 16 parallel blocks (one per batch); compaction by one thread per block
// over the 196-entry smem mask (cheap, parallel across batches).
// ============================================================
__global__ void cover_kernel() {
    __shared__ unsigned char mask[HW4];
    const int b = blockIdx.x;
    const int tid = threadIdx.x;

    for (int i = tid; i < HW4; i += 256) mask[i] = 0;
    __syncthreads();

    const int n = g_cnt[b];
    for (int r = 0; r < n; ++r) {
        const int4 rc = g_rect[g_list[b][r]];
        if (rc.x > rc.y) continue;
        const int g0 = rc.x >> 2, g1 = rc.y >> 2;
        const int cols = g1 - g0 + 1;
        const int tot = (rc.w - rc.z + 1) * cols;
        for (int i = tid; i < tot; i += 256) {
            int ry = i / cols, cx = i - ry * cols;
            mask[(rc.z + ry) * 7 + g0 + cx] = 1;   // idempotent
        }
    }
    __syncthreads();

    if (tid == 0) {
        int cnt = 0;
        for (int i = 0; i < HW4; ++i)
            if (mask[i]) g_load[b][cnt++] = i;
        g_nload[b] = cnt;
    }
}

// ============================================================
// Kernel 2 (HBM-bound, pure stream, 82% DRAM): temporal mean over
// covered groups. Flat work list: item -> (b, c, covered group).
// Every thread loads 32 float4s (4 independent chains), writes one group.
// Offsets recomputed in-block from g_nload (16 adds) — no prefix kernel.
// ============================================================
__global__ void __launch_bounds__(256) mean_kernel(const float* __restrict__ x) {
    __shared__ int soff[BB + 1];
    __shared__ int sn4[BB];
    if (threadIdx.x == 0) {
        int acc = 0;
        #pragma unroll
        for (int b = 0; b < BB; ++b) {
            soff[b] = acc;
            int n = g_nload[b];
            sn4[b] = n;
            acc += n * CC;
        }
        soff[BB] = acc;
    }
    __syncthreads();

    const int item = blockIdx.x * 256 + threadIdx.x;
    if (item >= soff[BB]) return;

    int b = 0;
    while (item >= soff[b + 1]) ++b;
    const int rel = item - soff[b];
    const int n4 = sn4[b];
    const int c = rel / n4;
    const int j = rel - c * n4;
    const int p4 = g_load[b][j];
    const int plane = b * CC + c;

    const float4* __restrict__ xp =
        (const float4*)x + (size_t)plane * (TT * HW4) + p4;

    float4 a0 = make_float4(0.f, 0.f, 0.f, 0.f);
    float4 a1 = a0, a2 = a0, a3 = a0;
    #pragma unroll
    for (int t = 0; t < 8; ++t) {
        float4 v0 = __ldcs(xp + (t)      * HW4);
        float4 v1 = __ldcs(xp + (t + 8)  * HW4);
        float4 v2 = __ldcs(xp + (t + 16) * HW4);
        float4 v3 = __ldcs(xp + (t + 24) * HW4);
        a0.x += v0.x; a0.y += v0.y; a0.z += v0.z; a0.w += v0.w;
        a1.x += v1.x; a1.y += v1.y; a1.z += v1.z; a1.w += v1.w;
        a2.x += v2.x; a2.y += v2.y; a2.z += v2.z; a2.w += v2.w;
        a3.x += v3.x; a3.y += v3.y; a3.z += v3.z; a3.w += v3.w;
    }
    const float inv = 1.0f / (float)TT;
    g_feat4[(size_t)plane * HW4 + p4] = make_float4(
        (a0.x + a1.x + a2.x + a3.x) * inv,
        (a0.y + a1.y + a2.y + a3.y) * inv,
        (a0.z + a1.z + a2.z + a3.z) * inv,
        (a0.w + a1.w + a2.w + a3.w) * inv);
}

// ============================================================
// Kernel 2b: ROI pooling, inverted layout: block = (roi, channel-chunk).
// wmap staged ONCE in smem per block (reused by 24 channels); each warp
// dots one channel with coalesced consecutive-p feat reads (L2-resident).
// All pixels in a roi's rect are covered by construction (rect ⊆ union).
// ============================================================
__global__ void __launch_bounds__(256) roi_kernel() {
    __shared__ float wm_s[HW];
    const int roi = blockIdx.x;
    const int cg  = blockIdx.y;            // 0..21, 24 channels each
    const int tid = threadIdx.x, warp = tid >> 5, lane = tid & 31;

    const int4 rc = g_rect[roi];
    if (rc.x > rc.y) {                     // empty roi: zeros
        for (int ci = warp; ci < CPB; ci += 8)
            if (lane == 0) g_rmean[roi * CC + cg * CPB + ci] = 0.f;
        return;
    }

    for (int p = tid; p < HW; p += 256) wm_s[p] = g_wmap[roi * HW + p];
    __syncthreads();

    const int b = g_broi[roi];
    const float* __restrict__ feat = (const float*)g_feat4;

    const int xx = rc.x + lane;            // width <= 28 < 32
    const bool on = (xx <= rc.y);

    for (int ci = warp; ci < CPB; ci += 8) {
        const int c = cg * CPB + ci;
        const float* __restrict__ fp = feat + (size_t)(b * CC + c) * HW;
        float acc = 0.f;
        for (int yy = rc.z; yy <= rc.w; ++yy) {
            int p = yy * WW + xx;
            if (on) acc += wm_s[p] * fp[p];   // fp: coalesced across lanes
        }
        #pragma unroll
        for (int o = 16; o; o >>= 1) acc += __shfl_xor_sync(0xffffffffu, acc, o);
        if (lane == 0) g_rmean[roi * CC + c] = acc;
    }
}

// ============================================================
// Kernel 3: layer-1 GEMV partials, 16-way j-split (1024 blocks).
// ============================================================
__global__ void __launch_bounds__(256) mlp_kernel(
    const float* __restrict__ w1, const float* __restrict__ b1) {
    __shared__ float r[4 * CC];
    __shared__ float part[8][4];
    const int tid = threadIdx.x, warp = tid >> 5, lane = tid & 31;
    const int roi0 = blockIdx.x * 4;
    const int jg = blockIdx.y;

    for (int i = tid; i < 4 * CC; i += 256)
        r[i] = g_rmean[roi0 * CC + i];
    __syncthreads();

    const int j = jg * 8 + warp;
    const float* __restrict__ wr = w1 + j * CC;

    float a0 = 0.f, a1 = 0.f, a2 = 0.f, a3 = 0.f;
    #pragma unroll 4
    for (int k = lane; k < CC; k += 32) {
        float w = wr[k];
        a0 += w * r[k];
        a1 += w * r[CC + k];
        a2 += w * r[2 * CC + k];
        a3 += w * r[3 * CC + k];
    }
    #pragma unroll
    for (int o = 16; o; o >>= 1) {
        a0 += __shfl_xor_sync(0xffffffffu, a0, o);
        a1 += __shfl_xor_sync(0xffffffffu, a1, o);
        a2 += __shfl_xor_sync(0xffffffffu, a2, o);
        a3 += __shfl_xor_sync(0xffffffffu, a3, o);
    }
    if (lane == 0) {
        float bj = b1[j], vj = g_v[j];
        part[warp][0] = vj * fmaxf(a0 + bj, 0.f);
        part[warp][1] = vj * fmaxf(a1 + bj, 0.f);
        part[warp][2] = vj * fmaxf(a2 + bj, 0.f);
        part[warp][3] = vj * fmaxf(a3 + bj, 0.f);
    }
    __syncthreads();
    if (tid < 4) {
        float s = 0.f;
        #pragma unroll
        for (int w = 0; w < 8; ++w) s += part[w][tid];
        g_part[(roi0 + tid) * 16 + jg] = s;
    }
}

// ============================================================
// Kernel 4: finalize. out[roi] = c0 + sum_jg part[roi][jg].
// ============================================================
__global__ void fin_kernel(float* __restrict__ out) {
    int roi = threadIdx.x;
    float s = g_c0;
    #pragma unroll
    for (int jg = 0; jg < 16; ++jg) s += g_part[roi * 16 + jg];
    out[roi] = s;
}

// ============================================================
// launch
// ============================================================
extern "C" void kernel_launch(void* const* d_in, const int* in_sizes, int n_in,
                              void* d_out, int out_size) {
    const float* x    = (const float*)d_in[0];
    const float* bbox = (const float*)d_in[1];
    const float* w1   = (const float*)d_in[2];
    const float* b1   = (const float*)d_in[3];
    const float* w2   = (const float*)d_in[4];
    const float* b2   = (const float*)d_in[5];
    const float* w3   = (const float*)d_in[6];
    const float* b3   = (const float*)d_in[7];
    float* out = (float*)d_out;

    wmap_kernel<<<RR, 256>>>(bbox);
    prep_kernel<<<2, 128>>>(bbox, w2, b2, w3, b3);
    cover_kernel<<<BB, 256>>>();
    mean_kernel<<<MEAN_BLOCKS, 256>>>(x);
    roi_kernel<<<dim3(RR, CC / CPB), 256>>>();
    mlp_kernel<<<dim3(RR / 4, 16), 256>>>(w1, b1);
    fin_kernel<<<1, RR>>>(out);
}

// round 9
// speedup vs baseline: 1.7979x; 1.1062x over previous
#include <cuda_runtime.h>
#include <cuda_bf16.h>

#define BB 16
#define CC 528
#define TT 32
#define HH 28
#define WW 28
#define HW 784          // 28*28
#define HW4 196         // HW/4 (7 float4 groups per row)
#define RR 256
#define MAX_ITEMS (BB*CC*HW4)   // 1,655,808
#define MEAN_BLOCKS ((MAX_ITEMS + 255) / 256)  // 6468
#define CPB 48          // channels per roi-block (11 * 48 = 528)
#define CPW 6           // channels per warp (8 warps * 6 = 48)

// ---- device scratch (no allocations allowed) ----
__device__ float  g_wmap[RR * HW];    // per-ROI dense weight map over 28x28
__device__ int4   g_rect[RR];         // xmin, xmax, ymin, ymax (inclusive); xmin>xmax => empty
__device__ int    g_list[BB][RR];     // ROI indices per batch
__device__ int    g_cnt[BB];
__device__ int    g_broi[RR];         // batch index per roi
__device__ float  g_rmean[RR * CC];   // pooled ROI features
__device__ float  g_v[128];           // folded w3 @ w2  (layers 2+3 are linear)
__device__ float  g_c0;               // folded bias
__device__ float  g_part[RR * 16];    // per-(roi, j-group) partial sums
__device__ int    g_load[BB][HW4];    // per-batch compacted float4-group indices
__device__ int    g_nload[BB];        // count per batch
__device__ float4 g_feat4[BB * CC * HW4];  // temporal-mean features (26.5 MB, L2-resident)

// ============================================================
// Kernel 0 (fused): blocks 0..255 build per-ROI weight map + rect;
// block 256 builds per-batch ROI lists; block 257 folds v = w3@w2.
// ============================================================
__global__ void wp_kernel(const float* __restrict__ bbox,
                          const float* __restrict__ w2,
                          const float* __restrict__ b2,
                          const float* __restrict__ w3,
                          const float* __restrict__ b3) {
    const int tid = threadIdx.x;

    if (blockIdx.x == 256) {                 // per-batch roi lists
        int b = tid;
        if (b < BB) {
            int cnt = 0;
            for (int r = 0; r < RR; ++r) {
                int rb = (int)bbox[r * 5];
                if (rb == b) g_list[b][cnt++] = r;
            }
            g_cnt[b] = cnt;
        }
        return;
    }
    if (blockIdx.x == 257) {                 // fold layers 2+3
        int j = tid;
        if (j < 128) {
            float acc = 0.f;
            #pragma unroll
            for (int i = 0; i < 32; ++i) acc += w3[i] * w2[i * 128 + j];
            g_v[j] = acc;
            if (j == 0) {
                float c = b3[0];
                #pragma unroll
                for (int i = 0; i < 32; ++i) c += w3[i] * b2[i];
                g_c0 = c;
            }
        }
        return;
    }

    // ---- wmap for roi = blockIdx.x ----
    __shared__ float smap[HW];
    __shared__ int sxmin, sxmax, symin, symax;
    const int roi = blockIdx.x;

    for (int p = tid; p < HW; p += 256) smap[p] = 0.f;
    if (tid == 0) { sxmin = 1000; symin = 1000; sxmax = -1; symax = -1; }
    __syncthreads();

    const float* bb = bbox + roi * 5;
    const float x1 = bb[1] * 0.0625f - 0.5f;
    const float y1 = bb[2] * 0.0625f - 0.5f;
    const float x2 = bb[3] * 0.0625f - 0.5f;
    const float y2 = bb[4] * 0.0625f - 0.5f;
    const float bw = (x2 - x1) * 0.125f;   // /OUT(8)
    const float bh = (y2 - y1) * 0.125f;

    const int iy = tid >> 4, ix = tid & 15;
    const float sy = y1 + ((float)iy * 0.5f + 0.25f) * bh;  // off=(i+0.5)/SR
    const float sx = x1 + ((float)ix * 0.5f + 0.25f) * bw;

    const bool valid = (sy > -1.0f) && (sy < (float)HH) && (sx > -1.0f) && (sx < (float)WW);
    if (valid) {
        float yc = fminf(fmaxf(sy, 0.f), (float)(HH - 1));
        float xc = fminf(fmaxf(sx, 0.f), (float)(WW - 1));
        int y0 = (int)floorf(yc);
        int x0 = (int)floorf(xc);
        int y1i = min(y0 + 1, HH - 1);
        int x1i = min(x0 + 1, WW - 1);
        float ly = yc - (float)y0, lx = xc - (float)x0;
        float hy = 1.f - ly, hx = 1.f - lx;
        const float s = 1.0f / 256.0f;   // uniform mean over 16x16 samples
        atomicAdd(&smap[y0 * WW + x0],  hy * hx * s);
        atomicAdd(&smap[y0 * WW + x1i], hy * lx * s);
        atomicAdd(&smap[y1i * WW + x0], ly * hx * s);
        atomicAdd(&smap[y1i * WW + x1i], ly * lx * s);
        atomicMin(&sxmin, x0); atomicMax(&sxmax, x1i);
        atomicMin(&symin, y0); atomicMax(&symax, y1i);
    }
    __syncthreads();

    for (int p = tid; p < HW; p += 256) g_wmap[roi * HW + p] = smap[p];
    if (tid == 0) {
        g_rect[roi] = make_int4(sxmin, sxmax, symin, symax);
        g_broi[roi] = (int)bb[0];
    }
}

// ============================================================
// Kernel 1: per-batch union of ROI rects at float4-group granularity.
// ============================================================
__global__ void cover_kernel() {
    __shared__ unsigned char mask[HW4];
    const int b = blockIdx.x;
    const int tid = threadIdx.x;

    for (int i = tid; i < HW4; i += 256) mask[i] = 0;
    __syncthreads();

    const int n = g_cnt[b];
    for (int r = 0; r < n; ++r) {
        const int4 rc = g_rect[g_list[b][r]];
        if (rc.x > rc.y) continue;
        const int g0 = rc.x >> 2, g1 = rc.y >> 2;
        const int cols = g1 - g0 + 1;
        const int tot = (rc.w - rc.z + 1) * cols;
        for (int i = tid; i < tot; i += 256) {
            int ry = i / cols, cx = i - ry * cols;
            mask[(rc.z + ry) * 7 + g0 + cx] = 1;   // idempotent
        }
    }
    __syncthreads();

    if (tid == 0) {
        int cnt = 0;
        for (int i = 0; i < HW4; ++i)
            if (mask[i]) g_load[b][cnt++] = i;
        g_nload[b] = cnt;
    }
}

// ============================================================
// Kernel 2 (HBM-bound, 81% DRAM — unchanged): temporal mean over
// covered groups, flat work list, 4 independent accumulator chains.
// ============================================================
__global__ void __launch_bounds__(256) mean_kernel(const float* __restrict__ x) {
    __shared__ int soff[BB + 1];
    __shared__ int sn4[BB];
    if (threadIdx.x == 0) {
        int acc = 0;
        #pragma unroll
        for (int b = 0; b < BB; ++b) {
            soff[b] = acc;
            int n = g_nload[b];
            sn4[b] = n;
            acc += n * CC;
        }
        soff[BB] = acc;
    }
    __syncthreads();

    const int item = blockIdx.x * 256 + threadIdx.x;
    if (item >= soff[BB]) return;

    int b = 0;
    while (item >= soff[b + 1]) ++b;
    const int rel = item - soff[b];
    const int n4 = sn4[b];
    const int c = rel / n4;
    const int j = rel - c * n4;
    const int p4 = g_load[b][j];
    const int plane = b * CC + c;

    const float4* __restrict__ xp =
        (const float4*)x + (size_t)plane * (TT * HW4) + p4;

    float4 a0 = make_float4(0.f, 0.f, 0.f, 0.f);
    float4 a1 = a0, a2 = a0, a3 = a0;
    #pragma unroll
    for (int t = 0; t < 8; ++t) {
        float4 v0 = __ldcs(xp + (t)      * HW4);
        float4 v1 = __ldcs(xp + (t + 8)  * HW4);
        float4 v2 = __ldcs(xp + (t + 16) * HW4);
        float4 v3 = __ldcs(xp + (t + 24) * HW4);
        a0.x += v0.x; a0.y += v0.y; a0.z += v0.z; a0.w += v0.w;
        a1.x += v1.x; a1.y += v1.y; a1.z += v1.z; a1.w += v1.w;
        a2.x += v2.x; a2.y += v2.y; a2.z += v2.z; a2.w += v2.w;
        a3.x += v3.x; a3.y += v3.y; a3.z += v3.z; a3.w += v3.w;
    }
    const float inv = 1.0f / (float)TT;
    g_feat4[(size_t)plane * HW4 + p4] = make_float4(
        (a0.x + a1.x + a2.x + a3.x) * inv,
        (a0.y + a1.y + a2.y + a3.y) * inv,
        (a0.z + a1.z + a2.z + a3.z) * inv,
        (a0.w + a1.w + a2.w + a3.w) * inv);
}

// ============================================================
// Kernel 2b: ROI pooling with 6-channel ILP per warp.
// Block = (roi, 48-channel chunk); warp w owns channels w*6+{0..5}:
// 6 independent L2 load streams per row, wmap smem-staged (48x reuse).
// ============================================================
__global__ void __launch_bounds__(256) roi_kernel() {
    __shared__ float wm_s[HW];
    const int roi = blockIdx.x;
    const int cg  = blockIdx.y;            // 0..10
    const int tid = threadIdx.x, warp = tid >> 5, lane = tid & 31;

    const int4 rc = g_rect[roi];
    if (rc.x > rc.y) {                     // empty roi (uniform branch)
        if (tid < CPB) g_rmean[roi * CC + cg * CPB + tid] = 0.f;
        return;
    }

    for (int p = tid; p < HW; p += 256) wm_s[p] = g_wmap[roi * HW + p];
    __syncthreads();

    const int b = g_broi[roi];
    const int c0 = cg * CPB + warp * CPW;
    const float* __restrict__ feat = (const float*)g_feat4;
    const float* __restrict__ fp0 = feat + (size_t)(b * CC + c0) * HW;

    const int xx = rc.x + lane;            // width <= 28 < 32
    const bool on = (xx <= rc.y);

    float a0 = 0.f, a1 = 0.f, a2 = 0.f, a3 = 0.f, a4 = 0.f, a5 = 0.f;
    for (int yy = rc.z; yy <= rc.w; ++yy) {
        const int p = yy * WW + xx;
        if (on) {
            const float w = wm_s[p];
            a0 += w * fp0[p];
            a1 += w * fp0[HW + p];
            a2 += w * fp0[2 * HW + p];
            a3 += w * fp0[3 * HW + p];
            a4 += w * fp0[4 * HW + p];
            a5 += w * fp0[5 * HW + p];
        }
    }
    #pragma unroll
    for (int o = 16; o; o >>= 1) {
        a0 += __shfl_xor_sync(0xffffffffu, a0, o);
        a1 += __shfl_xor_sync(0xffffffffu, a1, o);
        a2 += __shfl_xor_sync(0xffffffffu, a2, o);
        a3 += __shfl_xor_sync(0xffffffffu, a3, o);
        a4 += __shfl_xor_sync(0xffffffffu, a4, o);
        a5 += __shfl_xor_sync(0xffffffffu, a5, o);
    }
    if (lane == 0) {
        float* __restrict__ dst = g_rmean + roi * CC + c0;
        dst[0] = a0; dst[1] = a1; dst[2] = a2;
        dst[3] = a3; dst[4] = a4; dst[5] = a5;
    }
}

// ============================================================
// Kernel 3: layer-1 GEMV partials, 16-way j-split (1024 blocks).
// ============================================================
__global__ void __launch_bounds__(256) mlp_kernel(
    const float* __restrict__ w1, const float* __restrict__ b1) {
    __shared__ float r[4 * CC];
    __shared__ float part[8][4];
    const int tid = threadIdx.x, warp = tid >> 5, lane = tid & 31;
    const int roi0 = blockIdx.x * 4;
    const int jg = blockIdx.y;

    for (int i = tid; i < 4 * CC; i += 256)
        r[i] = g_rmean[roi0 * CC + i];
    __syncthreads();

    const int j = jg * 8 + warp;
    const float* __restrict__ wr = w1 + j * CC;

    float a0 = 0.f, a1 = 0.f, a2 = 0.f, a3 = 0.f;
    #pragma unroll 4
    for (int k = lane; k < CC; k += 32) {
        float w = wr[k];
        a0 += w * r[k];
        a1 += w * r[CC + k];
        a2 += w * r[2 * CC + k];
        a3 += w * r[3 * CC + k];
    }
    #pragma unroll
    for (int o = 16; o; o >>= 1) {
        a0 += __shfl_xor_sync(0xffffffffu, a0, o);
        a1 += __shfl_xor_sync(0xffffffffu, a1, o);
        a2 += __shfl_xor_sync(0xffffffffu, a2, o);
        a3 += __shfl_xor_sync(0xffffffffu, a3, o);
    }
    if (lane == 0) {
        float bj = b1[j], vj = g_v[j];
        part[warp][0] = vj * fmaxf(a0 + bj, 0.f);
        part[warp][1] = vj * fmaxf(a1 + bj, 0.f);
        part[warp][2] = vj * fmaxf(a2 + bj, 0.f);
        part[warp][3] = vj * fmaxf(a3 + bj, 0.f);
    }
    __syncthreads();
    if (tid < 4) {
        float s = 0.f;
        #pragma unroll
        for (int w = 0; w < 8; ++w) s += part[w][tid];
        g_part[(roi0 + tid) * 16 + jg] = s;
    }
}

// ============================================================
// Kernel 4: finalize. out[roi] = c0 + sum_jg part[roi][jg].
// ============================================================
__global__ void fin_kernel(float* __restrict__ out) {
    int roi = threadIdx.x;
    float s = g_c0;
    #pragma unroll
    for (int jg = 0; jg < 16; ++jg) s += g_part[roi * 16 + jg];
    out[roi] = s;
}

// ============================================================
// launch
// ============================================================
extern "C" void kernel_launch(void* const* d_in, const int* in_sizes, int n_in,
                              void* d_out, int out_size) {
    const float* x    = (const float*)d_in[0];
    const float* bbox = (const float*)d_in[1];
    const float* w1   = (const float*)d_in[2];
    const float* b1   = (const float*)d_in[3];
    const float* w2   = (const float*)d_in[4];
    const float* b2   = (const float*)d_in[5];
    const float* w3   = (const float*)d_in[6];
    const float* b3   = (const float*)d_in[7];
    float* out = (float*)d_out;

    wp_kernel<<<258, 256>>>(bbox, w2, b2, w3, b3);
    cover_kernel<<<BB, 256>>>();
    mean_kernel<<<MEAN_BLOCKS, 256>>>(x);
    roi_kernel<<<dim3(RR, CC / CPB), 256>>>();
    mlp_kernel<<<dim3(RR / 4, 16), 256>>>(w1, b1);
    fin_kernel<<<1, RR>>>(out);
}

// round 10
// speedup vs baseline: 1.8850x; 1.0485x over previous
#include <cuda_runtime.h>
#include <cuda_bf16.h>

#define BB 16
#define CC 528
#define TT 32
#define HH 28
#define WW 28
#define HW 784          // 28*28
#define HW4 196         // HW/4 (7 float4 groups per row)
#define RR 256
#define MAX_ITEMS (BB*CC*HW4)   // 1,655,808
#define MEAN_BLOCKS ((MAX_ITEMS + 255) / 256)  // 6468
#define CPB 88          // channels per roi-block (6 * 88 = 528)
#define CPW 11          // channels per warp (8 warps * 11 = 88)

// ---- device scratch (no allocations allowed) ----
__device__ float  g_wmap[RR * HW];    // per-ROI dense weight map over 28x28 (zero outside support)
__device__ int4   g_rect[RR];         // padded rect: xmin,xmax,ymin,ymax (inclusive); xmin>xmax => empty
__device__ int    g_broi[RR];         // batch index per roi
__device__ float  g_rmean[RR * CC];   // pooled ROI features
__device__ float  g_v[128];           // folded w3 @ w2  (layers 2+3 are linear)
__device__ float  g_c0;               // folded bias
__device__ float  g_part[RR * 16];    // per-(roi, j-group) partial sums
__device__ int    g_load[BB][HW4];    // per-batch compacted float4-group indices
__device__ int    g_nload[BB];        // count per batch
__device__ float4 g_feat4[BB * CC * HW4];  // temporal-mean features (26.5 MB, L2-resident)
                                           // uncovered entries stay 0 (zero-initialized, never written)

// ============================================================
// Kernel 0 (fully fused prep), 273 blocks:
//   blocks 0..255  : per-ROI dense weight map (wmap)
//   blocks 256..271: per-batch cover: analytic rects + union mask + load list
//   block  272     : fold v = w3@w2, c0 = w3@b2 + b3
// cover doesn't need wmap: rect bounds are separable in x/y and computed
// directly from bbox. Stored rects are padded by 1px (clamped) so any
// 1-ulp divergence vs the wmap support is harmless: padded pixels have
// wmap == 0 and feat == 0 there, contributing exactly 0.
// ============================================================
__global__ void wp_kernel(const float* __restrict__ bbox,
                          const float* __restrict__ w2,
                          const float* __restrict__ b2,
                          const float* __restrict__ w3,
                          const float* __restrict__ b3) {
    const int tid = threadIdx.x;
    const int blk = blockIdx.x;

    if (blk == 272) {                        // fold layers 2+3
        int j = tid;
        if (j < 128) {
            float acc = 0.f;
            #pragma unroll
            for (int i = 0; i < 32; ++i) acc += w3[i] * w2[i * 128 + j];
            g_v[j] = acc;
            if (j == 0) {
                float c = b3[0];
                #pragma unroll
                for (int i = 0; i < 32; ++i) c += w3[i] * b2[i];
                g_c0 = c;
            }
        }
        return;
    }

    if (blk >= 256) {                        // ---- cover for batch b ----
        const int b = blk - 256;
        __shared__ unsigned char mask[HW4];
        __shared__ int4 srect[RR];           // unpadded rects of this batch's rois
        __shared__ int scnt;

        for (int i = tid; i < HW4; i += 256) mask[i] = 0;
        if (tid == 0) scnt = 0;
        __syncthreads();

        // one thread per roi: analytic rect (separable x/y bounds)
        {
            const float* bb = bbox + tid * 5;
            const int rb = (int)bb[0];
            if (rb == b) {
                const float x1 = bb[1] * 0.0625f - 0.5f;
                const float y1 = bb[2] * 0.0625f - 0.5f;
                const float x2 = bb[3] * 0.0625f - 0.5f;
                const float y2 = bb[4] * 0.0625f - 0.5f;
                const float bw = (x2 - x1) * 0.125f;
                const float bh = (y2 - y1) * 0.125f;
                int xmin = 1000, xmax = -1, ymin = 1000, ymax = -1;
                #pragma unroll
                for (int i = 0; i < 16; ++i) {
                    const float o = (float)i * 0.5f + 0.25f;
                    const float sx = x1 + o * bw;
                    if (sx > -1.0f && sx < (float)WW) {
                        float xc = fminf(fmaxf(sx, 0.f), (float)(WW - 1));
                        int x0 = (int)floorf(xc);
                        int x1i = min(x0 + 1, WW - 1);
                        xmin = min(xmin, x0); xmax = max(xmax, x1i);
                    }
                    const float sy = y1 + o * bh;
                    if (sy > -1.0f && sy < (float)HH) {
                        float yc = fminf(fmaxf(sy, 0.f), (float)(HH - 1));
                        int y0 = (int)floorf(yc);
                        int y1i = min(y0 + 1, HH - 1);
                        ymin = min(ymin, y0); ymax = max(ymax, y1i);
                    }
                }
                int4 rc_pad, rc_raw;
                if (xmax < 0 || ymax < 0) {
                    rc_pad = make_int4(1000, -1, 1000, -1);
                    rc_raw = rc_pad;
                } else {
                    rc_raw = make_int4(xmin, xmax, ymin, ymax);
                    rc_pad = make_int4(max(xmin - 1, 0), min(xmax + 1, WW - 1),
                                       max(ymin - 1, 0), min(ymax + 1, HH - 1));
                }
                g_rect[tid] = rc_pad;
                g_broi[tid] = rb;
                if (rc_raw.x <= rc_raw.y) {
                    int slot = atomicAdd(&scnt, 1);
                    srect[slot] = rc_raw;    // order irrelevant: mask union is idempotent
                }
            }
        }
        __syncthreads();

        const int n = scnt;
        for (int r = 0; r < n; ++r) {
            const int4 rc = srect[r];
            const int g0 = rc.x >> 2, g1 = rc.y >> 2;
            const int cols = g1 - g0 + 1;
            const int tot = (rc.w - rc.z + 1) * cols;
            for (int i = tid; i < tot; i += 256) {
                int ry = i / cols, cx = i - ry * cols;
                mask[(rc.z + ry) * 7 + g0 + cx] = 1;
            }
        }
        __syncthreads();

        if (tid == 0) {
            int cnt = 0;
            for (int i = 0; i < HW4; ++i)
                if (mask[i]) g_load[b][cnt++] = i;
            g_nload[b] = cnt;
        }
        return;
    }

    // ---- wmap for roi = blk ----
    __shared__ float smap[HW];
    const int roi = blk;

    for (int p = tid; p < HW; p += 256) smap[p] = 0.f;
    __syncthreads();

    const float* bb = bbox + roi * 5;
    const float x1 = bb[1] * 0.0625f - 0.5f;
    const float y1 = bb[2] * 0.0625f - 0.5f;
    const float x2 = bb[3] * 0.0625f - 0.5f;
    const float y2 = bb[4] * 0.0625f - 0.5f;
    const float bw = (x2 - x1) * 0.125f;   // /OUT(8)
    const float bh = (y2 - y1) * 0.125f;

    const int iy = tid >> 4, ix = tid & 15;
    const float sy = y1 + ((float)iy * 0.5f + 0.25f) * bh;  // off=(i+0.5)/SR
    const float sx = x1 + ((float)ix * 0.5f + 0.25f) * bw;

    const bool valid = (sy > -1.0f) && (sy < (float)HH) && (sx > -1.0f) && (sx < (float)WW);
    if (valid) {
        float yc = fminf(fmaxf(sy, 0.f), (float)(HH - 1));
        float xc = fminf(fmaxf(sx, 0.f), (float)(WW - 1));
        int y0 = (int)floorf(yc);
        int x0 = (int)floorf(xc);
        int y1i = min(y0 + 1, HH - 1);
        int x1i = min(x0 + 1, WW - 1);
        float ly = yc - (float)y0, lx = xc - (float)x0;
        float hy = 1.f - ly, hx = 1.f - lx;
        const float s = 1.0f / 256.0f;   // uniform mean over 16x16 samples
        atomicAdd(&smap[y0 * WW + x0],  hy * hx * s);
        atomicAdd(&smap[y0 * WW + x1i], hy * lx * s);
        atomicAdd(&smap[y1i * WW + x0], ly * hx * s);
        atomicAdd(&smap[y1i * WW + x1i], ly * lx * s);
    }
    __syncthreads();

    for (int p = tid; p < HW; p += 256) g_wmap[roi * HW + p] = smap[p];
}

// ============================================================
// Kernel 1 (HBM-bound, 81% DRAM — unchanged): temporal mean over
// covered groups, flat work list, 4 independent accumulator chains.
// ============================================================
__global__ void __launch_bounds__(256) mean_kernel(const float* __restrict__ x) {
    __shared__ int soff[BB + 1];
    __shared__ int sn4[BB];
    if (threadIdx.x == 0) {
        int acc = 0;
        #pragma unroll
        for (int b = 0; b < BB; ++b) {
            soff[b] = acc;
            int n = g_nload[b];
            sn4[b] = n;
            acc += n * CC;
        }
        soff[BB] = acc;
    }
    __syncthreads();

    const int item = blockIdx.x * 256 + threadIdx.x;
    if (item >= soff[BB]) return;

    int b = 0;
    while (item >= soff[b + 1]) ++b;
    const int rel = item - soff[b];
    const int n4 = sn4[b];
    const int c = rel / n4;
    const int j = rel - c * n4;
    const int p4 = g_load[b][j];
    const int plane = b * CC + c;

    const float4* __restrict__ xp =
        (const float4*)x + (size_t)plane * (TT * HW4) + p4;

    float4 a0 = make_float4(0.f, 0.f, 0.f, 0.f);
    float4 a1 = a0, a2 = a0, a3 = a0;
    #pragma unroll
    for (int t = 0; t < 8; ++t) {
        float4 v0 = __ldcs(xp + (t)      * HW4);
        float4 v1 = __ldcs(xp + (t + 8)  * HW4);
        float4 v2 = __ldcs(xp + (t + 16) * HW4);
        float4 v3 = __ldcs(xp + (t + 24) * HW4);
        a0.x += v0.x; a0.y += v0.y; a0.z += v0.z; a0.w += v0.w;
        a1.x += v1.x; a1.y += v1.y; a1.z += v1.z; a1.w += v1.w;
        a2.x += v2.x; a2.y += v2.y; a2.z += v2.z; a2.w += v2.w;
        a3.x += v3.x; a3.y += v3.y; a3.z += v3.z; a3.w += v3.w;
    }
    const float inv = 1.0f / (float)TT;
    g_feat4[(size_t)plane * HW4 + p4] = make_float4(
        (a0.x + a1.x + a2.x + a3.x) * inv,
        (a0.y + a1.y + a2.y + a3.y) * inv,
        (a0.z + a1.z + a2.z + a3.z) * inv,
        (a0.w + a1.w + a2.w + a3.w) * inv);
}

// ============================================================
// Kernel 2: ROI pooling with 11-channel ILP per warp.
// Block = (roi, 88-channel chunk); warp w owns channels w*11+{0..10}:
// 11 independent L2 load streams per row, wmap smem-staged (88x reuse).
// ============================================================
__global__ void __launch_bounds__(256) roi_kernel() {
    __shared__ float wm_s[HW];
    const int roi = blockIdx.x;
    const int cg  = blockIdx.y;            // 0..5
    const int tid = threadIdx.x, warp = tid >> 5, lane = tid & 31;

    const int4 rc = g_rect[roi];
    if (rc.x > rc.y) {                     // empty roi (uniform branch)
        if (tid < CPB) g_rmean[roi * CC + cg * CPB + tid] = 0.f;
        return;
    }

    for (int p = tid; p < HW; p += 256) wm_s[p] = g_wmap[roi * HW + p];
    __syncthreads();

    const int b = g_broi[roi];
    const int c0 = cg * CPB + warp * CPW;
    const float* __restrict__ fp0 =
        (const float*)g_feat4 + (size_t)(b * CC + c0) * HW;

    const int xx = rc.x + lane;            // width <= 28 < 32
    const bool on = (xx <= rc.y);

    float a[CPW];
    #pragma unroll
    for (int k = 0; k < CPW; ++k) a[k] = 0.f;

    for (int yy = rc.z; yy <= rc.w; ++yy) {
        const int p = yy * WW + xx;
        if (on) {
            const float w = wm_s[p];
            #pragma unroll
            for (int k = 0; k < CPW; ++k)
                a[k] += w * fp0[k * HW + p];   // 11 concurrent L2 streams
        }
    }
    #pragma unroll
    for (int k = 0; k < CPW; ++k) {
        #pragma unroll
        for (int o = 16; o; o >>= 1) a[k] += __shfl_xor_sync(0xffffffffu, a[k], o);
    }
    if (lane == 0) {
        float* __restrict__ dst = g_rmean + roi * CC + c0;
        #pragma unroll
        for (int k = 0; k < CPW; ++k) dst[k] = a[k];
    }
}

// ============================================================
// Kernel 3: layer-1 GEMV partials, 16-way j-split (1024 blocks).
// ============================================================
__global__ void __launch_bounds__(256) mlp_kernel(
    const float* __restrict__ w1, const float* __restrict__ b1) {
    __shared__ float r[4 * CC];
    __shared__ float part[8][4];
    const int tid = threadIdx.x, warp = tid >> 5, lane = tid & 31;
    const int roi0 = blockIdx.x * 4;
    const int jg = blockIdx.y;

    for (int i = tid; i < 4 * CC; i += 256)
        r[i] = g_rmean[roi0 * CC + i];
    __syncthreads();

    const int j = jg * 8 + warp;
    const float* __restrict__ wr = w1 + j * CC;

    float a0 = 0.f, a1 = 0.f, a2 = 0.f, a3 = 0.f;
    #pragma unroll 4
    for (int k = lane; k < CC; k += 32) {
        float w = wr[k];
        a0 += w * r[k];
        a1 += w * r[CC + k];
        a2 += w * r[2 * CC + k];
        a3 += w * r[3 * CC + k];
    }
    #pragma unroll
    for (int o = 16; o; o >>= 1) {
        a0 += __shfl_xor_sync(0xffffffffu, a0, o);
        a1 += __shfl_xor_sync(0xffffffffu, a1, o);
        a2 += __shfl_xor_sync(0xffffffffu, a2, o);
        a3 += __shfl_xor_sync(0xffffffffu, a3, o);
    }
    if (lane == 0) {
        float bj = b1[j], vj = g_v[j];
        part[warp][0] = vj * fmaxf(a0 + bj, 0.f);
        part[warp][1] = vj * fmaxf(a1 + bj, 0.f);
        part[warp][2] = vj * fmaxf(a2 + bj, 0.f);
        part[warp][3] = vj * fmaxf(a3 + bj, 0.f);
    }
    __syncthreads();
    if (tid < 4) {
        float s = 0.f;
        #pragma unroll
        for (int w = 0; w < 8; ++w) s += part[w][tid];
        g_part[(roi0 + tid) * 16 + jg] = s;
    }
}

// ============================================================
// Kernel 4: finalize. out[roi] = c0 + sum_jg part[roi][jg].
// ============================================================
__global__ void fin_kernel(float* __restrict__ out) {
    int roi = threadIdx.x;
    float s = g_c0;
    #pragma unroll
    for (int jg = 0; jg < 16; ++jg) s += g_part[roi * 16 + jg];
    out[roi] = s;
}

// ============================================================
// launch
// ============================================================
extern "C" void kernel_launch(void* const* d_in, const int* in_sizes, int n_in,
                              void* d_out, int out_size) {
    const float* x    = (const float*)d_in[0];
    const float* bbox = (const float*)d_in[1];
    const float* w1   = (const float*)d_in[2];
    const float* b1   = (const float*)d_in[3];
    const float* w2   = (const float*)d_in[4];
    const float* b2   = (const float*)d_in[5];
    const float* w3   = (const float*)d_in[6];
    const float* b3   = (const float*)d_in[7];
    float* out = (float*)d_out;

    wp_kernel<<<273, 256>>>(bbox, w2, b2, w3, b3);
    mean_kernel<<<MEAN_BLOCKS, 256>>>(x);
    roi_kernel<<<dim3(RR, CC / CPB), 256>>>();
    mlp_kernel<<<dim3(RR / 4, 16), 256>>>(w1, b1);
    fin_kernel<<<1, RR>>>(out);
}

// round 11
// speedup vs baseline: 1.9147x; 1.0158x over previous
#include <cuda_runtime.h>
#include <cuda_bf16.h>

#define BB 16
#define CC 528
#define CC4 132         // CC/4
#define TT 32
#define HH 28
#define WW 28
#define HW 784          // 28*28
#define HW4 196         // HW/4 (7 float4 groups per row)
#define RR 256
#define MAX_ITEMS (BB*CC*HW4)   // 1,655,808
#define MEAN_BLOCKS ((MAX_ITEMS + 255) / 256)  // 6468
#define CPB 88          // channels per roi-block (6 * 88 = 528)
#define CPW 11          // channels per warp (8 warps * 11 = 88)

// ---- device scratch (no allocations allowed) ----
__device__ float  g_wmap[RR * HW];    // per-ROI dense weight map over 28x28 (zero outside support)
__device__ int4   g_rect[RR];         // padded rect: xmin,xmax,ymin,ymax (inclusive); xmin>xmax => empty
__device__ int    g_broi[RR];         // batch index per roi
__device__ float4 g_rmean4[RR * CC4]; // pooled ROI features (float4 layout for vector MLP)
__device__ float  g_v[128];           // folded w3 @ w2  (layers 2+3 are linear)
__device__ float  g_c0;               // folded bias
__device__ float  g_part[RR * 16];    // per-(roi, j-group) partial sums
__device__ int    g_load[BB][HW4];    // per-batch compacted float4-group indices
__device__ int    g_nload[BB];        // count per batch
__device__ float4 g_feat4[BB * CC * HW4];  // temporal-mean features (26.5 MB, L2-resident)
                                           // uncovered entries stay 0 (zero-initialized, never written)

// ============================================================
// Kernel 0 (fully fused prep), 273 blocks:
//   blocks 0..255  : per-ROI dense weight map (wmap)
//   blocks 256..271: per-batch cover: analytic rects + union mask + load list
//   block  272     : fold v = w3@w2, c0 = w3@b2 + b3
// Stored rects padded 1px: padded pixels have wmap == 0 and feat == 0,
// contributing exactly 0 (immunizes against 1-ulp rect/wmap divergence).
// ============================================================
__global__ void wp_kernel(const float* __restrict__ bbox,
                          const float* __restrict__ w2,
                          const float* __restrict__ b2,
                          const float* __restrict__ w3,
                          const float* __restrict__ b3) {
    const int tid = threadIdx.x;
    const int blk = blockIdx.x;

    if (blk == 272) {                        // fold layers 2+3
        int j = tid;
        if (j < 128) {
            float acc = 0.f;
            #pragma unroll
            for (int i = 0; i < 32; ++i) acc += w3[i] * w2[i * 128 + j];
            g_v[j] = acc;
            if (j == 0) {
                float c = b3[0];
                #pragma unroll
                for (int i = 0; i < 32; ++i) c += w3[i] * b2[i];
                g_c0 = c;
            }
        }
        return;
    }

    if (blk >= 256) {                        // ---- cover for batch b ----
        const int b = blk - 256;
        __shared__ unsigned char mask[HW4];
        __shared__ int4 srect[RR];           // unpadded rects of this batch's rois
        __shared__ int scnt;

        for (int i = tid; i < HW4; i += 256) mask[i] = 0;
        if (tid == 0) scnt = 0;
        __syncthreads();

        // one thread per roi: analytic rect (separable x/y bounds)
        {
            const float* bb = bbox + tid * 5;
            const int rb = (int)bb[0];
            if (rb == b) {
                const float x1 = bb[1] * 0.0625f - 0.5f;
                const float y1 = bb[2] * 0.0625f - 0.5f;
                const float x2 = bb[3] * 0.0625f - 0.5f;
                const float y2 = bb[4] * 0.0625f - 0.5f;
                const float bw = (x2 - x1) * 0.125f;
                const float bh = (y2 - y1) * 0.125f;
                int xmin = 1000, xmax = -1, ymin = 1000, ymax = -1;
                #pragma unroll
                for (int i = 0; i < 16; ++i) {
                    const float o = (float)i * 0.5f + 0.25f;
                    const float sx = x1 + o * bw;
                    if (sx > -1.0f && sx < (float)WW) {
                        float xc = fminf(fmaxf(sx, 0.f), (float)(WW - 1));
                        int x0 = (int)floorf(xc);
                        int x1i = min(x0 + 1, WW - 1);
                        xmin = min(xmin, x0); xmax = max(xmax, x1i);
                    }
                    const float sy = y1 + o * bh;
                    if (sy > -1.0f && sy < (float)HH) {
                        float yc = fminf(fmaxf(sy, 0.f), (float)(HH - 1));
                        int y0 = (int)floorf(yc);
                        int y1i = min(y0 + 1, HH - 1);
                        ymin = min(ymin, y0); ymax = max(ymax, y1i);
                    }
                }
                int4 rc_pad, rc_raw;
                if (xmax < 0 || ymax < 0) {
                    rc_pad = make_int4(1000, -1, 1000, -1);
                    rc_raw = rc_pad;
                } else {
                    rc_raw = make_int4(xmin, xmax, ymin, ymax);
                    rc_pad = make_int4(max(xmin - 1, 0), min(xmax + 1, WW - 1),
                                       max(ymin - 1, 0), min(ymax + 1, HH - 1));
                }
                g_rect[tid] = rc_pad;
                g_broi[tid] = rb;
                if (rc_raw.x <= rc_raw.y) {
                    int slot = atomicAdd(&scnt, 1);
                    srect[slot] = rc_raw;    // order irrelevant: mask union idempotent
                }
            }
        }
        __syncthreads();

        const int n = scnt;
        for (int r = 0; r < n; ++r) {
            const int4 rc = srect[r];
            const int g0 = rc.x >> 2, g1 = rc.y >> 2;
            const int cols = g1 - g0 + 1;
            const int tot = (rc.w - rc.z + 1) * cols;
            for (int i = tid; i < tot; i += 256) {
                int ry = i / cols, cx = i - ry * cols;
                mask[(rc.z + ry) * 7 + g0 + cx] = 1;
            }
        }
        __syncthreads();

        if (tid == 0) {
            int cnt = 0;
            for (int i = 0; i < HW4; ++i)
                if (mask[i]) g_load[b][cnt++] = i;
            g_nload[b] = cnt;
        }
        return;
    }

    // ---- wmap for roi = blk ----
    __shared__ float smap[HW];
    const int roi = blk;

    for (int p = tid; p < HW; p += 256) smap[p] = 0.f;
    __syncthreads();

    const float* bb = bbox + roi * 5;
    const float x1 = bb[1] * 0.0625f - 0.5f;
    const float y1 = bb[2] * 0.0625f - 0.5f;
    const float x2 = bb[3] * 0.0625f - 0.5f;
    const float y2 = bb[4] * 0.0625f - 0.5f;
    const float bw = (x2 - x1) * 0.125f;   // /OUT(8)
    const float bh = (y2 - y1) * 0.125f;

    const int iy = tid >> 4, ix = tid & 15;
    const float sy = y1 + ((float)iy * 0.5f + 0.25f) * bh;  // off=(i+0.5)/SR
    const float sx = x1 + ((float)ix * 0.5f + 0.25f) * bw;

    const bool valid = (sy > -1.0f) && (sy < (float)HH) && (sx > -1.0f) && (sx < (float)WW);
    if (valid) {
        float yc = fminf(fmaxf(sy, 0.f), (float)(HH - 1));
        float xc = fminf(fmaxf(sx, 0.f), (float)(WW - 1));
        int y0 = (int)floorf(yc);
        int x0 = (int)floorf(xc);
        int y1i = min(y0 + 1, HH - 1);
        int x1i = min(x0 + 1, WW - 1);
        float ly = yc - (float)y0, lx = xc - (float)x0;
        float hy = 1.f - ly, hx = 1.f - lx;
        const float s = 1.0f / 256.0f;   // uniform mean over 16x16 samples
        atomicAdd(&smap[y0 * WW + x0],  hy * hx * s);
        atomicAdd(&smap[y0 * WW + x1i], hy * lx * s);
        atomicAdd(&smap[y1i * WW + x0], ly * hx * s);
        atomicAdd(&smap[y1i * WW + x1i], ly * lx * s);
    }
    __syncthreads();

    for (int p = tid; p < HW; p += 256) g_wmap[roi * HW + p] = smap[p];
}

// ============================================================
// Kernel 1 (HBM-bound, 81% DRAM — unchanged): temporal mean over
// covered groups, flat work list, 4 independent accumulator chains.
// ============================================================
__global__ void __launch_bounds__(256) mean_kernel(const float* __restrict__ x) {
    __shared__ int soff[BB + 1];
    __shared__ int sn4[BB];
    if (threadIdx.x == 0) {
        int acc = 0;
        #pragma unroll
        for (int b = 0; b < BB; ++b) {
            soff[b] = acc;
            int n = g_nload[b];
            sn4[b] = n;
            acc += n * CC;
        }
        soff[BB] = acc;
    }
    __syncthreads();

    const int item = blockIdx.x * 256 + threadIdx.x;
    if (item >= soff[BB]) return;

    int b = 0;
    while (item >= soff[b + 1]) ++b;
    const int rel = item - soff[b];
    const int n4 = sn4[b];
    const int c = rel / n4;
    const int j = rel - c * n4;
    const int p4 = g_load[b][j];
    const int plane = b * CC + c;

    const float4* __restrict__ xp =
        (const float4*)x + (size_t)plane * (TT * HW4) + p4;

    float4 a0 = make_float4(0.f, 0.f, 0.f, 0.f);
    float4 a1 = a0, a2 = a0, a3 = a0;
    #pragma unroll
    for (int t = 0; t < 8; ++t) {
        float4 v0 = __ldcs(xp + (t)      * HW4);
        float4 v1 = __ldcs(xp + (t + 8)  * HW4);
        float4 v2 = __ldcs(xp + (t + 16) * HW4);
        float4 v3 = __ldcs(xp + (t + 24) * HW4);
        a0.x += v0.x; a0.y += v0.y; a0.z += v0.z; a0.w += v0.w;
        a1.x += v1.x; a1.y += v1.y; a1.z += v1.z; a1.w += v1.w;
        a2.x += v2.x; a2.y += v2.y; a2.z += v2.z; a2.w += v2.w;
        a3.x += v3.x; a3.y += v3.y; a3.z += v3.z; a3.w += v3.w;
    }
    const float inv = 1.0f / (float)TT;
    g_feat4[(size_t)plane * HW4 + p4] = make_float4(
        (a0.x + a1.x + a2.x + a3.x) * inv,
        (a0.y + a1.y + a2.y + a3.y) * inv,
        (a0.z + a1.z + a2.z + a3.z) * inv,
        (a0.w + a1.w + a2.w + a3.w) * inv);
}

// ============================================================
// Kernel 2: ROI pooling with 11-channel ILP per warp, y-loop unrolled 2x
// (22 concurrent L2 streams). wmap smem-staged (88x reuse per block).
// ============================================================
__global__ void __launch_bounds__(256) roi_kernel() {
    __shared__ float wm_s[HW];
    const int roi = blockIdx.x;
    const int cg  = blockIdx.y;            // 0..5
    const int tid = threadIdx.x, warp = tid >> 5, lane = tid & 31;

    const int4 rc = g_rect[roi];
    float* __restrict__ rmean = (float*)g_rmean4;
    if (rc.x > rc.y) {                     // empty roi (uniform branch)
        if (tid < CPB) rmean[roi * CC + cg * CPB + tid] = 0.f;
        return;
    }

    for (int p = tid; p < HW; p += 256) wm_s[p] = g_wmap[roi * HW + p];
    __syncthreads();

    const int b = g_broi[roi];
    const int c0 = cg * CPB + warp * CPW;
    const float* __restrict__ fp0 =
        (const float*)g_feat4 + (size_t)(b * CC + c0) * HW;

    const int xx = rc.x + lane;            // width <= 28 < 32
    const bool on = (xx <= rc.y);

    float a[CPW];
    #pragma unroll
    for (int k = 0; k < CPW; ++k) a[k] = 0.f;

    #pragma unroll 2
    for (int yy = rc.z; yy <= rc.w; ++yy) {
        const int p = yy * WW + xx;
        if (on) {
            const float w = wm_s[p];
            #pragma unroll
            for (int k = 0; k < CPW; ++k)
                a[k] += w * fp0[k * HW + p];   // concurrent L2 streams
        }
    }
    #pragma unroll
    for (int k = 0; k < CPW; ++k) {
        #pragma unroll
        for (int o = 16; o; o >>= 1) a[k] += __shfl_xor_sync(0xffffffffu, a[k], o);
    }
    if (lane == 0) {
        float* __restrict__ dst = rmean + roi * CC + c0;
        #pragma unroll
        for (int k = 0; k < CPW; ++k) dst[k] = a[k];
    }
}

// ============================================================
// Kernel 3: layer-1 GEMV partials, float4-vectorized, 16-way j-split.
// Each lane: 1 LDG.128 of w1 + 4 LDS.128 of r per 16 FMAs.
// ============================================================
__global__ void __launch_bounds__(256) mlp_kernel(
    const float* __restrict__ w1, const float* __restrict__ b1) {
    __shared__ float4 r4[4 * CC4];
    __shared__ float part[8][4];
    const int tid = threadIdx.x, warp = tid >> 5, lane = tid & 31;
    const int roi0 = blockIdx.x * 4;
    const int jg = blockIdx.y;

    for (int i = tid; i < 4 * CC4; i += 256)
        r4[i] = g_rmean4[roi0 * CC4 + i];
    __syncthreads();

    const int j = jg * 8 + warp;
    const float4* __restrict__ wr = (const float4*)(w1 + j * CC);  // 528*4B row: 16B-aligned

    float a0 = 0.f, a1 = 0.f, a2 = 0.f, a3 = 0.f;
    for (int k = lane; k < CC4; k += 32) {
        const float4 w = wr[k];
        const float4 v0 = r4[k];
        const float4 v1 = r4[CC4 + k];
        const float4 v2 = r4[2 * CC4 + k];
        const float4 v3 = r4[3 * CC4 + k];
        a0 += w.x * v0.x + w.y * v0.y + w.z * v0.z + w.w * v0.w;
        a1 += w.x * v1.x + w.y * v1.y + w.z * v1.z + w.w * v1.w;
        a2 += w.x * v2.x + w.y * v2.y + w.z * v2.z + w.w * v2.w;
        a3 += w.x * v3.x + w.y * v3.y + w.z * v3.z + w.w * v3.w;
    }
    #pragma unroll
    for (int o = 16; o; o >>= 1) {
        a0 += __shfl_xor_sync(0xffffffffu, a0, o);
        a1 += __shfl_xor_sync(0xffffffffu, a1, o);
        a2 += __shfl_xor_sync(0xffffffffu, a2, o);
        a3 += __shfl_xor_sync(0xffffffffu, a3, o);
    }
    if (lane == 0) {
        float bj = b1[j], vj = g_v[j];
        part[warp][0] = vj * fmaxf(a0 + bj, 0.f);
        part[warp][1] = vj * fmaxf(a1 + bj, 0.f);
        part[warp][2] = vj * fmaxf(a2 + bj, 0.f);
        part[warp][3] = vj * fmaxf(a3 + bj, 0.f);
    }
    __syncthreads();
    if (tid < 4) {
        float s = 0.f;
        #pragma unroll
        for (int w = 0; w < 8; ++w) s += part[w][tid];
        g_part[(roi0 + tid) * 16 + jg] = s;
    }
}

// ============================================================
// Kernel 4: finalize. out[roi] = c0 + sum_jg part[roi][jg].
// ============================================================
__global__ void fin_kernel(float* __restrict__ out) {
    int roi = threadIdx.x;
    float s = g_c0;
    #pragma unroll
    for (int jg = 0; jg < 16; ++jg) s += g_part[roi * 16 + jg];
    out[roi] = s;
}

// ============================================================
// launch
// ============================================================
extern "C" void kernel_launch(void* const* d_in, const int* in_sizes, int n_in,
                              void* d_out, int out_size) {
    const float* x    = (const float*)d_in[0];
    const float* bbox = (const float*)d_in[1];
    const float* w1   = (const float*)d_in[2];
    const float* b1   = (const float*)d_in[3];
    const float* w2   = (const float*)d_in[4];
    const float* b2   = (const float*)d_in[5];
    const float* w3   = (const float*)d_in[6];
    const float* b3   = (const float*)d_in[7];
    float* out = (float*)d_out;

    wp_kernel<<<273, 256>>>(bbox, w2, b2, w3, b3);
    mean_kernel<<<MEAN_BLOCKS, 256>>>(x);
    roi_kernel<<<dim3(RR, CC / CPB), 256>>>();
    mlp_kernel<<<dim3(RR / 4, 16), 256>>>(w1, b1);
    fin_kernel<<<1, RR>>>(out);
}